// round 1
// baseline (speedup 1.0000x reference)
#include <cuda_runtime.h>

#define BB 2
#define SS 2048
#define HH 16
#define DD 64
#define DE 1024

// Projected Q/K/V scratch: [b*H + h][s][d]
__device__ float g_Q[BB*HH*SS*DD];
__device__ float g_K[BB*HH*SS*DD];
__device__ float g_V[BB*HH*SS*DD];

// ---------------------------------------------------------------------------
// Projection: y[bh][s][e] = sum_d x[b][s][h*64+d] * W[e][d]   (torch Linear)
// grid (S/64, H, B), 256 threads. 4x4 register microtile per thread.
// ---------------------------------------------------------------------------
__global__ __launch_bounds__(256) void proj_kernel(const float* __restrict__ x,
                                                   const float* __restrict__ W,
                                                   int which) {
    __shared__ float Xs[64][65];
    __shared__ float Ws[64][65];
    float* y = (which == 0) ? g_Q : (which == 1) ? g_K : g_V;

    int b = blockIdx.z, h = blockIdx.y, s0 = blockIdx.x * 64;
    int t = threadIdx.x;

    for (int i = t; i < 4096; i += 256) Ws[i >> 6][i & 63] = W[i];
    const float* xb = x + ((size_t)(b * SS + s0)) * DE + h * DD;
    for (int i = t; i < 4096; i += 256) {
        int r = i >> 6, d = i & 63;
        Xs[r][d] = xb[(size_t)r * DE + d];
    }
    __syncthreads();

    int tc = t & 15, tr = t >> 4;
    float acc[4][4];
#pragma unroll
    for (int i = 0; i < 4; i++)
#pragma unroll
        for (int j = 0; j < 4; j++) acc[i][j] = 0.f;

#pragma unroll 8
    for (int d = 0; d < 64; d++) {
        float xr[4], wc[4];
#pragma unroll
        for (int i = 0; i < 4; i++) xr[i] = Xs[tr * 4 + i][d];
#pragma unroll
        for (int j = 0; j < 4; j++) wc[j] = Ws[tc * 4 + j][d];
#pragma unroll
        for (int i = 0; i < 4; i++)
#pragma unroll
            for (int j = 0; j < 4; j++) acc[i][j] += xr[i] * wc[j];
    }

    float* yb = y + ((size_t)(b * HH + h) * SS + s0) * DD;
#pragma unroll
    for (int i = 0; i < 4; i++) {
        float4 v4 = make_float4(acc[i][0], acc[i][1], acc[i][2], acc[i][3]);
        *reinterpret_cast<float4*>(yb + (size_t)(tr * 4 + i) * DD + tc * 4) = v4;
    }
}

// ---------------------------------------------------------------------------
// Flash attention, fp32 SIMT.
// grid (S/64, H, B), 256 threads, dynamic smem:
//   Qt [64 d][68]  (d-major, scaled by 1/8)
//   Kt [64 d][68]  (d-major; reused as P [64 row][68] after scores)
//   Vs [64 k][68]  (k-major)
// Thread (tr,tc) owns 4 q-rows (tr*4+i) x 4 out-cols / 4 keys (tc*4+j).
// Row-group = 16 lane-contiguous threads -> shfl_xor width-16 reductions.
// ---------------------------------------------------------------------------
#define SMEM_FLOATS (3 * 64 * 68)

__global__ __launch_bounds__(256) void attn_kernel(float* __restrict__ out) {
    extern __shared__ float smem[];
    float* Qt = smem;                 // 64*68
    float* Kt = smem + 64 * 68;       // K (d-major), then P (row-major)
    float* Vs = smem + 2 * 64 * 68;   // V (k-major)

    int b = blockIdx.z, h = blockIdx.y, s0 = blockIdx.x * 64;
    int t = threadIdx.x;
    size_t bh = (size_t)(b * HH + h);
    const float* Qb = g_Q + bh * SS * DD + (size_t)s0 * DD;
    const float* Kb = g_K + bh * SS * DD;
    const float* Vb = g_V + bh * SS * DD;

    // Q tile, transposed + scaled
    for (int i = t; i < 4096; i += 256) {
        int r = i >> 6, d = i & 63;
        Qt[d * 68 + r] = Qb[i] * 0.125f;
    }

    int tc = t & 15, tr = t >> 4;
    float o[4][4], m[4], l[4];
#pragma unroll
    for (int i = 0; i < 4; i++) {
        m[i] = -1e30f; l[i] = 0.f;
#pragma unroll
        for (int j = 0; j < 4; j++) o[i][j] = 0.f;
    }

    for (int kt = 0; kt < SS / 64; kt++) {
        __syncthreads();  // prior P/V reads (and Qt writes on iter 0) complete
        const float* Kb0 = Kb + (size_t)kt * 64 * DD;
        const float* Vb0 = Vb + (size_t)kt * 64 * DD;
        for (int i = t; i < 4096; i += 256) {
            int k = i >> 6, d = i & 63;
            Kt[d * 68 + k] = Kb0[i];
            Vs[k * 68 + d] = Vb0[i];
        }
        __syncthreads();

        // S = Q K^T (4x4 microtile)
        float s[4][4];
#pragma unroll
        for (int i = 0; i < 4; i++)
#pragma unroll
            for (int j = 0; j < 4; j++) s[i][j] = 0.f;

#pragma unroll 8
        for (int d = 0; d < 64; d++) {
            float qv[4];
#pragma unroll
            for (int i = 0; i < 4; i++) qv[i] = Qt[d * 68 + tr * 4 + i];
            float4 kv = *reinterpret_cast<const float4*>(Kt + d * 68 + tc * 4);
#pragma unroll
            for (int i = 0; i < 4; i++) {
                s[i][0] += qv[i] * kv.x;
                s[i][1] += qv[i] * kv.y;
                s[i][2] += qv[i] * kv.z;
                s[i][3] += qv[i] * kv.w;
            }
        }

        // streaming softmax (per row group of 16 threads)
        float p[4][4];
#pragma unroll
        for (int i = 0; i < 4; i++) {
            float tm = fmaxf(fmaxf(s[i][0], s[i][1]), fmaxf(s[i][2], s[i][3]));
#pragma unroll
            for (int x = 1; x < 16; x <<= 1)
                tm = fmaxf(tm, __shfl_xor_sync(0xffffffffu, tm, x));
            float mn = fmaxf(m[i], tm);
            float cf = __expf(m[i] - mn);
            m[i] = mn;
            float srow = 0.f;
#pragma unroll
            for (int j = 0; j < 4; j++) {
                p[i][j] = __expf(s[i][j] - mn);
                srow += p[i][j];
            }
#pragma unroll
            for (int x = 1; x < 16; x <<= 1)
                srow += __shfl_xor_sync(0xffffffffu, srow, x);
            l[i] = l[i] * cf + srow;
#pragma unroll
            for (int j = 0; j < 4; j++) o[i][j] *= cf;
        }

        __syncthreads();  // all threads done reading Kt-as-K
        // write P over Kt: Ps[row][k]
#pragma unroll
        for (int i = 0; i < 4; i++) {
            *reinterpret_cast<float4*>(Kt + (tr * 4 + i) * 68 + tc * 4) =
                make_float4(p[i][0], p[i][1], p[i][2], p[i][3]);
        }
        __syncthreads();

        // O += P @ V
#pragma unroll 8
        for (int k = 0; k < 64; k++) {
            float pr[4];
#pragma unroll
            for (int i = 0; i < 4; i++) pr[i] = Kt[(tr * 4 + i) * 68 + k];
            float4 vv = *reinterpret_cast<const float4*>(Vs + k * 68 + tc * 4);
#pragma unroll
            for (int i = 0; i < 4; i++) {
                o[i][0] += pr[i] * vv.x;
                o[i][1] += pr[i] * vv.y;
                o[i][2] += pr[i] * vv.z;
                o[i][3] += pr[i] * vv.w;
            }
        }
    }

    // out[b][s0+row][h*64 + col]
#pragma unroll
    for (int i = 0; i < 4; i++) {
        int row = tr * 4 + i;
        float inv = 1.f / l[i];
        float4 v4 = make_float4(o[i][0] * inv, o[i][1] * inv,
                                o[i][2] * inv, o[i][3] * inv);
        *reinterpret_cast<float4*>(out + ((size_t)(b * SS + s0 + row)) * DE +
                                   h * DD + tc * 4) = v4;
    }
}

extern "C" void kernel_launch(void* const* d_in, const int* in_sizes, int n_in,
                              void* d_out, int out_size) {
    const float* k  = (const float*)d_in[0];
    const float* q  = (const float*)d_in[1];
    const float* v  = (const float*)d_in[2];
    const float* Wk = (const float*)d_in[3];
    const float* Wq = (const float*)d_in[4];
    const float* Wv = (const float*)d_in[5];
    float* out = (float*)d_out;

    dim3 grid(SS / 64, HH, BB);
    proj_kernel<<<grid, 256>>>(q, Wq, 0);
    proj_kernel<<<grid, 256>>>(k, Wk, 1);
    proj_kernel<<<grid, 256>>>(v, Wv, 2);

    static const size_t smem_bytes = SMEM_FLOATS * sizeof(float);  // 52224
    cudaFuncSetAttribute(attn_kernel,
                         cudaFuncAttributeMaxDynamicSharedMemorySize,
                         (int)smem_bytes);
    attn_kernel<<<grid, 256, smem_bytes>>>(out);
}

// round 4
// speedup vs baseline: 4.3270x; 4.3270x over previous
#include <cuda_runtime.h>
#include <cuda_fp16.h>
#include <cstdint>
#include <cstddef>

#define BB 2
#define SS 2048
#define HH 16
#define DD 64
#define DE 1024

// Projected Q/K/V in fp16, layout [b*H + h][s][d]. Q pre-scaled by 1/8.
__device__ __half g_Q[BB*HH*SS*DD];
__device__ __half g_K[BB*HH*SS*DD];
__device__ __half g_V[BB*HH*SS*DD];

// ---------------------------------------------------------------------------
// Fused projection: one launch does Q,K,V. grid (S/64, H, 3*B).
// y[bh][s][e] = sum_d x[b][s][h*64+d] * W[e][d]  (fp32 math, fp16 store)
// ---------------------------------------------------------------------------
__global__ __launch_bounds__(256) void proj_kernel(const float* __restrict__ xq,
                                                   const float* __restrict__ xk,
                                                   const float* __restrict__ xv,
                                                   const float* __restrict__ Wq,
                                                   const float* __restrict__ Wk,
                                                   const float* __restrict__ Wv) {
    __shared__ float Xs[64][65];
    __shared__ float Ws[64][65];

    int which = blockIdx.z / BB;          // 0=Q 1=K 2=V
    int b = blockIdx.z % BB;
    int h = blockIdx.y, s0 = blockIdx.x * 64;
    int t = threadIdx.x;

    const float* x = (which == 0) ? xq : (which == 1) ? xk : xv;
    const float* W = (which == 0) ? Wq : (which == 1) ? Wk : Wv;
    __half* y      = (which == 0) ? g_Q : (which == 1) ? g_K : g_V;
    float sc = (which == 0) ? 0.125f : 1.0f;   // 1/sqrt(64) folded into Q

    for (int i = t; i < 4096; i += 256) Ws[i >> 6][i & 63] = W[i];
    const float* xb = x + ((size_t)(b * SS + s0)) * DE + h * DD;
    for (int i = t; i < 4096; i += 256) {
        int r = i >> 6, d = i & 63;
        Xs[r][d] = xb[(size_t)r * DE + d];
    }
    __syncthreads();

    int tc = t & 15, tr = t >> 4;
    float acc[4][4];
#pragma unroll
    for (int i = 0; i < 4; i++)
#pragma unroll
        for (int j = 0; j < 4; j++) acc[i][j] = 0.f;

#pragma unroll 8
    for (int d = 0; d < 64; d++) {
        float xr[4], wc[4];
#pragma unroll
        for (int i = 0; i < 4; i++) xr[i] = Xs[tr * 4 + i][d];
#pragma unroll
        for (int j = 0; j < 4; j++) wc[j] = Ws[tc * 4 + j][d];
#pragma unroll
        for (int i = 0; i < 4; i++)
#pragma unroll
            for (int j = 0; j < 4; j++) acc[i][j] += xr[i] * wc[j];
    }

    __half* yb = y + ((size_t)(b * HH + h) * SS + s0) * DD;
#pragma unroll
    for (int i = 0; i < 4; i++) {
        __half2 h01 = __floats2half2_rn(acc[i][0] * sc, acc[i][1] * sc);
        __half2 h23 = __floats2half2_rn(acc[i][2] * sc, acc[i][3] * sc);
        __half2* p = reinterpret_cast<__half2*>(yb + (size_t)(tr * 4 + i) * DD + tc * 4);
        p[0] = h01;
        p[1] = h23;
    }
}

// ---------------------------------------------------------------------------
// Tensor-core flash attention (HMMA m16n8k16, fp16 in / fp32 acc).
// grid (S/64, H, B), 128 threads = 4 warps; warp w owns q-rows w*16..w*16+15.
// K-tile = 64 keys. Q fragments live in registers for the whole kernel.
// ---------------------------------------------------------------------------
#define KSTR 72   // smem row stride in halves (144B: conflict-free for frag loads)

__device__ __forceinline__ void mma16816(float* d, const uint32_t* a,
                                         uint32_t b0, uint32_t b1) {
    asm volatile(
        "mma.sync.aligned.m16n8k16.row.col.f32.f16.f16.f32 "
        "{%0,%1,%2,%3}, {%4,%5,%6,%7}, {%8,%9}, {%0,%1,%2,%3};\n"
        : "+f"(d[0]), "+f"(d[1]), "+f"(d[2]), "+f"(d[3])
        : "r"(a[0]), "r"(a[1]), "r"(a[2]), "r"(a[3]), "r"(b0), "r"(b1));
}

__device__ __forceinline__ uint32_t pack2(__half x, __half y) {
    __half2 t = __halves2half2(x, y);
    return *reinterpret_cast<uint32_t*>(&t);
}

__global__ __launch_bounds__(128) void attn_kernel(float* __restrict__ out) {
    __shared__ __align__(16) __half Ks[64 * KSTR];
    __shared__ __align__(16) __half Vs[64 * KSTR];

    int b = blockIdx.z, h = blockIdx.y, s0 = blockIdx.x * 64;
    int t = threadIdx.x, w = t >> 5, lane = t & 31;
    int g = lane >> 2, qr = lane & 3;
    size_t bh = (size_t)(b * HH + h);
    const __half* Qg = g_Q + bh * SS * DD + (size_t)(s0 + w * 16) * DD;
    const __half* Kg = g_K + bh * SS * DD;
    const __half* Vg = g_V + bh * SS * DD;

    // Q A-fragments (16 regs), persistent. m16n8k16 A layout:
    // a0:(row g, cols c..c+1) a1:(row g+8) a2:(row g, cols c+8..c+9) a3:(row g+8)
    uint32_t aQ[4][4];
#pragma unroll
    for (int kk = 0; kk < 4; kk++) {
        int c = kk * 16 + qr * 2;
        aQ[kk][0] = *(const uint32_t*)(Qg + (size_t)g * DD + c);
        aQ[kk][1] = *(const uint32_t*)(Qg + (size_t)(g + 8) * DD + c);
        aQ[kk][2] = *(const uint32_t*)(Qg + (size_t)g * DD + c + 8);
        aQ[kk][3] = *(const uint32_t*)(Qg + (size_t)(g + 8) * DD + c + 8);
    }

    float o[8][4];
#pragma unroll
    for (int dn = 0; dn < 8; dn++)
#pragma unroll
        for (int j = 0; j < 4; j++) o[dn][j] = 0.f;
    float m0 = -1e30f, m1 = -1e30f, l0 = 0.f, l1 = 0.f;

    for (int kt = 0; kt < SS / 64; kt++) {
        __syncthreads();
        const __half* K0 = Kg + (size_t)kt * 64 * DD;
        const __half* V0 = Vg + (size_t)kt * 64 * DD;
#pragma unroll
        for (int i = 0; i < 8; i++) {
            int idx = (i * 128 + t) * 4;      // halves, step 4
            int key = idx >> 6, d = idx & 63;
            *(float2*)&Ks[key * KSTR + d] = *(const float2*)(K0 + idx);
            *(float2*)&Vs[key * KSTR + d] = *(const float2*)(V0 + idx);
        }
        __syncthreads();

        // S = Q K^T  (8 n-tiles of 8 keys each)
        float s[8][4];
#pragma unroll
        for (int n = 0; n < 8; n++)
#pragma unroll
            for (int j = 0; j < 4; j++) s[n][j] = 0.f;

#pragma unroll
        for (int n = 0; n < 8; n++) {
            const __half* kr = Ks + (n * 8 + g) * KSTR;
#pragma unroll
            for (int kk = 0; kk < 4; kk++) {
                uint32_t b0 = *(const uint32_t*)(kr + kk * 16 + qr * 2);
                uint32_t b1 = *(const uint32_t*)(kr + kk * 16 + qr * 2 + 8);
                mma16816(s[n], aQ[kk], b0, b1);
            }
        }

        // streaming softmax; rows g (c0,c1) and g+8 (c2,c3), quad reduction
        float rx0 = -1e30f, rx1 = -1e30f;
#pragma unroll
        for (int n = 0; n < 8; n++) {
            rx0 = fmaxf(rx0, fmaxf(s[n][0], s[n][1]));
            rx1 = fmaxf(rx1, fmaxf(s[n][2], s[n][3]));
        }
        rx0 = fmaxf(rx0, __shfl_xor_sync(0xffffffffu, rx0, 1));
        rx0 = fmaxf(rx0, __shfl_xor_sync(0xffffffffu, rx0, 2));
        rx1 = fmaxf(rx1, __shfl_xor_sync(0xffffffffu, rx1, 1));
        rx1 = fmaxf(rx1, __shfl_xor_sync(0xffffffffu, rx1, 2));
        float mn0 = fmaxf(m0, rx0), mn1 = fmaxf(m1, rx1);
        float cf0 = __expf(m0 - mn0), cf1 = __expf(m1 - mn1);
        m0 = mn0; m1 = mn1;

        float sum0 = 0.f, sum1 = 0.f;
        uint32_t aP[4][4];   // P repacked as A-fragments for PV
#pragma unroll
        for (int n = 0; n < 8; n++) {
            float e0 = __expf(s[n][0] - mn0);
            float e1 = __expf(s[n][1] - mn0);
            float e2 = __expf(s[n][2] - mn1);
            float e3 = __expf(s[n][3] - mn1);
            sum0 += e0 + e1; sum1 += e2 + e3;
            aP[n >> 1][(n & 1) * 2 + 0] = pack2(__float2half_rn(e0), __float2half_rn(e1));
            aP[n >> 1][(n & 1) * 2 + 1] = pack2(__float2half_rn(e2), __float2half_rn(e3));
        }
        sum0 += __shfl_xor_sync(0xffffffffu, sum0, 1);
        sum0 += __shfl_xor_sync(0xffffffffu, sum0, 2);
        sum1 += __shfl_xor_sync(0xffffffffu, sum1, 1);
        sum1 += __shfl_xor_sync(0xffffffffu, sum1, 2);
        l0 = l0 * cf0 + sum0;
        l1 = l1 * cf1 + sum1;

#pragma unroll
        for (int dn = 0; dn < 8; dn++) {
            o[dn][0] *= cf0; o[dn][1] *= cf0;
            o[dn][2] *= cf1; o[dn][3] *= cf1;
        }

        // O += P @ V ; B frag: b0 = V[k0,k0+1][col], b1 = V[k0+8,k0+9][col]
#pragma unroll
        for (int dn = 0; dn < 8; dn++) {
            int col = dn * 8 + g;
#pragma unroll
            for (int kk = 0; kk < 4; kk++) {
                int k0 = kk * 16 + qr * 2;
                uint32_t b0 = pack2(Vs[k0 * KSTR + col], Vs[(k0 + 1) * KSTR + col]);
                uint32_t b1 = pack2(Vs[(k0 + 8) * KSTR + col], Vs[(k0 + 9) * KSTR + col]);
                mma16816(o[dn], aP[kk], b0, b1);
            }
        }
    }

    float inv0 = 1.f / l0, inv1 = 1.f / l1;
    int row0 = s0 + w * 16 + g, row1 = row0 + 8;
#pragma unroll
    for (int dn = 0; dn < 8; dn++) {
        int col = h * DD + dn * 8 + qr * 2;
        float2 v0 = make_float2(o[dn][0] * inv0, o[dn][1] * inv0);
        float2 v1 = make_float2(o[dn][2] * inv1, o[dn][3] * inv1);
        *(float2*)&out[(size_t)(b * SS + row0) * DE + col] = v0;
        *(float2*)&out[(size_t)(b * SS + row1) * DE + col] = v1;
    }
}

extern "C" void kernel_launch(void* const* d_in, const int* in_sizes, int n_in,
                              void* d_out, int out_size) {
    const float* k  = (const float*)d_in[0];
    const float* q  = (const float*)d_in[1];
    const float* v  = (const float*)d_in[2];
    const float* Wk = (const float*)d_in[3];
    const float* Wq = (const float*)d_in[4];
    const float* Wv = (const float*)d_in[5];
    float* out = (float*)d_out;

    dim3 pgrid(SS / 64, HH, 3 * BB);
    proj_kernel<<<pgrid, 256>>>(q, k, v, Wq, Wk, Wv);

    dim3 agrid(SS / 64, HH, BB);
    attn_kernel<<<agrid, 128>>>(out);
}

// round 5
// speedup vs baseline: 5.1808x; 1.1973x over previous
#include <cuda_runtime.h>
#include <cuda_fp16.h>
#include <cstdint>
#include <cstddef>

#define BB 2
#define SS 2048
#define HH 16
#define DD 64
#define DE 1024

// Projected Q/K/V in fp16, layout [b*H + h][s][d]. Q pre-scaled by 1/8.
__device__ __half g_Q[BB*HH*SS*DD];
__device__ __half g_K[BB*HH*SS*DD];
__device__ __half g_V[BB*HH*SS*DD];

#define KSTR 72   // smem row stride in halves (144B; 144%16==0, conflict-free rows)

__device__ __forceinline__ void mma16816(float* d, const uint32_t* a,
                                         uint32_t b0, uint32_t b1) {
    asm volatile(
        "mma.sync.aligned.m16n8k16.row.col.f32.f16.f16.f32 "
        "{%0,%1,%2,%3}, {%4,%5,%6,%7}, {%8,%9}, {%0,%1,%2,%3};\n"
        : "+f"(d[0]), "+f"(d[1]), "+f"(d[2]), "+f"(d[3])
        : "r"(a[0]), "r"(a[1]), "r"(a[2]), "r"(a[3]), "r"(b0), "r"(b1));
}

__device__ __forceinline__ void ldsm_x4(uint32_t& r0, uint32_t& r1,
                                        uint32_t& r2, uint32_t& r3, uint32_t a) {
    asm volatile("ldmatrix.sync.aligned.m8n8.x4.shared.b16 {%0,%1,%2,%3}, [%4];\n"
                 : "=r"(r0), "=r"(r1), "=r"(r2), "=r"(r3) : "r"(a));
}

__device__ __forceinline__ void ldsm_x4_t(uint32_t& r0, uint32_t& r1,
                                          uint32_t& r2, uint32_t& r3, uint32_t a) {
    asm volatile("ldmatrix.sync.aligned.m8n8.x4.trans.shared.b16 {%0,%1,%2,%3}, [%4];\n"
                 : "=r"(r0), "=r"(r1), "=r"(r2), "=r"(r3) : "r"(a));
}

__device__ __forceinline__ uint32_t smem_u32(const void* p) {
    return (uint32_t)__cvta_generic_to_shared(p);
}

__device__ __forceinline__ uint32_t pack2(__half x, __half y) {
    __half2 t = __halves2half2(x, y);
    return *reinterpret_cast<uint32_t*>(&t);
}

// ---------------------------------------------------------------------------
// Projection via hi/lo-split fp16 HMMA (effectively fp32-accurate).
// grid (S/64, H, 3*B), 128 threads = 4 warps; warp w computes 16 s-rows.
// Y[s][e] = sum_d X[s][d] * W[e][d];  acc = Xh*Wh + Xl*Wh + Xh*Wl (fp32 acc).
// ---------------------------------------------------------------------------
__global__ __launch_bounds__(128) void proj_kernel(const float* __restrict__ xq,
                                                   const float* __restrict__ xk,
                                                   const float* __restrict__ xv,
                                                   const float* __restrict__ Wq,
                                                   const float* __restrict__ Wk,
                                                   const float* __restrict__ Wv) {
    __shared__ __align__(16) __half Xh[64 * KSTR];
    __shared__ __align__(16) __half Xl[64 * KSTR];
    __shared__ __align__(16) __half Wh[64 * KSTR];
    __shared__ __align__(16) __half Wl[64 * KSTR];

    int which = blockIdx.z / BB;          // 0=Q 1=K 2=V
    int b = blockIdx.z % BB;
    int h = blockIdx.y, s0 = blockIdx.x * 64;
    int t = threadIdx.x, w = t >> 5, lane = t & 31;
    int g = lane >> 2, qr = lane & 3;

    const float* x = (which == 0) ? xq : (which == 1) ? xk : xv;
    const float* W = (which == 0) ? Wq : (which == 1) ? Wk : Wv;
    __half* y      = (which == 0) ? g_Q : (which == 1) ? g_K : g_V;
    float sc = (which == 0) ? 0.125f : 1.0f;   // 1/sqrt(64) folded into Q

    const float* xb = x + ((size_t)(b * SS + s0)) * DE + h * DD;
    for (int i = t; i < 4096; i += 128) {
        int r = i >> 6, d = i & 63;
        float xv_ = xb[(size_t)r * DE + d];
        __half hi = __float2half_rn(xv_);
        Xh[r * KSTR + d] = hi;
        Xl[r * KSTR + d] = __float2half_rn(xv_ - __half2float(hi));
        float wv_ = W[i];
        __half whi = __float2half_rn(wv_);
        Wh[r * KSTR + d] = whi;
        Wl[r * KSTR + d] = __float2half_rn(wv_ - __half2float(whi));
    }
    __syncthreads();

    // A fragments for this warp's 16 rows (hi and lo)
    uint32_t aH[4][4], aL[4][4];
    const __half* Xh0 = Xh + (w * 16) * KSTR;
    const __half* Xl0 = Xl + (w * 16) * KSTR;
#pragma unroll
    for (int kk = 0; kk < 4; kk++) {
        int c = kk * 16 + qr * 2;
        aH[kk][0] = *(const uint32_t*)(Xh0 + g * KSTR + c);
        aH[kk][1] = *(const uint32_t*)(Xh0 + (g + 8) * KSTR + c);
        aH[kk][2] = *(const uint32_t*)(Xh0 + g * KSTR + c + 8);
        aH[kk][3] = *(const uint32_t*)(Xh0 + (g + 8) * KSTR + c + 8);
        aL[kk][0] = *(const uint32_t*)(Xl0 + g * KSTR + c);
        aL[kk][1] = *(const uint32_t*)(Xl0 + (g + 8) * KSTR + c);
        aL[kk][2] = *(const uint32_t*)(Xl0 + g * KSTR + c + 8);
        aL[kk][3] = *(const uint32_t*)(Xl0 + (g + 8) * KSTR + c + 8);
    }

    float acc[8][4];
#pragma unroll
    for (int n = 0; n < 8; n++)
#pragma unroll
        for (int j = 0; j < 4; j++) acc[n][j] = 0.f;

    uint32_t whAddr = smem_u32(Wh) + ((lane & 7) * KSTR + (lane >> 3) * 8) * 2;
    uint32_t wlAddr = smem_u32(Wl) + ((lane & 7) * KSTR + (lane >> 3) * 8) * 2;
#pragma unroll
    for (int n = 0; n < 8; n++) {
#pragma unroll
        for (int kp = 0; kp < 2; kp++) {
            uint32_t off = (n * 8 * KSTR + kp * 32) * 2;
            uint32_t h00, h01, h10, h11, l00, l01, l10, l11;
            ldsm_x4(h00, h01, h10, h11, whAddr + off);
            ldsm_x4(l00, l01, l10, l11, wlAddr + off);
            mma16816(acc[n], aH[kp * 2], h00, h01);
            mma16816(acc[n], aL[kp * 2], h00, h01);
            mma16816(acc[n], aH[kp * 2], l00, l01);
            mma16816(acc[n], aH[kp * 2 + 1], h10, h11);
            mma16816(acc[n], aL[kp * 2 + 1], h10, h11);
            mma16816(acc[n], aH[kp * 2 + 1], l10, l11);
        }
    }

    __half* yb = y + ((size_t)(b * HH + h) * SS + s0) * DD;
    int r0 = w * 16 + g, r1 = r0 + 8;
#pragma unroll
    for (int n = 0; n < 8; n++) {
        int col = n * 8 + qr * 2;
        *(uint32_t*)(yb + (size_t)r0 * DD + col) =
            pack2(__float2half_rn(acc[n][0] * sc), __float2half_rn(acc[n][1] * sc));
        *(uint32_t*)(yb + (size_t)r1 * DD + col) =
            pack2(__float2half_rn(acc[n][2] * sc), __float2half_rn(acc[n][3] * sc));
    }
}

// ---------------------------------------------------------------------------
// Tensor-core flash attention (HMMA m16n8k16, fp16 in / fp32 acc).
// grid (S/64, H, B), 128 threads = 4 warps; warp w owns q-rows w*16..w*16+15.
// K fragments via ldmatrix.x4; V fragments via ldmatrix.x4.trans.
// ---------------------------------------------------------------------------
__global__ __launch_bounds__(128) void attn_kernel(float* __restrict__ out) {
    __shared__ __align__(16) __half Ks[64 * KSTR];
    __shared__ __align__(16) __half Vs[64 * KSTR];

    int b = blockIdx.z, h = blockIdx.y, s0 = blockIdx.x * 64;
    int t = threadIdx.x, w = t >> 5, lane = t & 31;
    int g = lane >> 2, qr = lane & 3;
    size_t bh = (size_t)(b * HH + h);
    const __half* Qg = g_Q + bh * SS * DD + (size_t)(s0 + w * 16) * DD;
    const __half* Kg = g_K + bh * SS * DD;
    const __half* Vg = g_V + bh * SS * DD;

    // Q A-fragments (16 regs), persistent.
    uint32_t aQ[4][4];
#pragma unroll
    for (int kk = 0; kk < 4; kk++) {
        int c = kk * 16 + qr * 2;
        aQ[kk][0] = *(const uint32_t*)(Qg + (size_t)g * DD + c);
        aQ[kk][1] = *(const uint32_t*)(Qg + (size_t)(g + 8) * DD + c);
        aQ[kk][2] = *(const uint32_t*)(Qg + (size_t)g * DD + c + 8);
        aQ[kk][3] = *(const uint32_t*)(Qg + (size_t)(g + 8) * DD + c + 8);
    }

    float o[8][4];
#pragma unroll
    for (int dn = 0; dn < 8; dn++)
#pragma unroll
        for (int j = 0; j < 4; j++) o[dn][j] = 0.f;
    float m0 = -1e30f, m1 = -1e30f, l0 = 0.f, l1 = 0.f;

    // ldmatrix base addresses (byte smem offsets)
    uint32_t kAddr = smem_u32(Ks) + ((lane & 7) * KSTR + (lane >> 3) * 8) * 2;
    uint32_t vAddr = smem_u32(Vs) + (lane * KSTR) * 2;

    for (int kt = 0; kt < SS / 64; kt++) {
        __syncthreads();
        const __half* K0 = Kg + (size_t)kt * 64 * DD;
        const __half* V0 = Vg + (size_t)kt * 64 * DD;
#pragma unroll
        for (int i = 0; i < 8; i++) {
            int idx = (i * 128 + t) * 4;      // halves, step 4
            int key = idx >> 6, d = idx & 63;
            *(float2*)&Ks[key * KSTR + d] = *(const float2*)(K0 + idx);
            *(float2*)&Vs[key * KSTR + d] = *(const float2*)(V0 + idx);
        }
        __syncthreads();

        // S = Q K^T  (8 n-tiles of 8 keys each); K frags via ldmatrix.x4
        float s[8][4];
#pragma unroll
        for (int n = 0; n < 8; n++) {
#pragma unroll
            for (int j = 0; j < 4; j++) s[n][j] = 0.f;
#pragma unroll
            for (int kp = 0; kp < 2; kp++) {
                uint32_t b00, b01, b10, b11;
                ldsm_x4(b00, b01, b10, b11, kAddr + (n * 8 * KSTR + kp * 32) * 2);
                mma16816(s[n], aQ[kp * 2], b00, b01);
                mma16816(s[n], aQ[kp * 2 + 1], b10, b11);
            }
        }

        // streaming softmax; rows g (c0,c1) and g+8 (c2,c3), quad reduction
        float rx0 = -1e30f, rx1 = -1e30f;
#pragma unroll
        for (int n = 0; n < 8; n++) {
            rx0 = fmaxf(rx0, fmaxf(s[n][0], s[n][1]));
            rx1 = fmaxf(rx1, fmaxf(s[n][2], s[n][3]));
        }
        rx0 = fmaxf(rx0, __shfl_xor_sync(0xffffffffu, rx0, 1));
        rx0 = fmaxf(rx0, __shfl_xor_sync(0xffffffffu, rx0, 2));
        rx1 = fmaxf(rx1, __shfl_xor_sync(0xffffffffu, rx1, 1));
        rx1 = fmaxf(rx1, __shfl_xor_sync(0xffffffffu, rx1, 2));
        float mn0 = fmaxf(m0, rx0), mn1 = fmaxf(m1, rx1);
        float cf0 = __expf(m0 - mn0), cf1 = __expf(m1 - mn1);
        m0 = mn0; m1 = mn1;

        float sum0 = 0.f, sum1 = 0.f;
        uint32_t aP[4][4];   // P repacked as A-fragments for PV
#pragma unroll
        for (int n = 0; n < 8; n++) {
            float e0 = __expf(s[n][0] - mn0);
            float e1 = __expf(s[n][1] - mn0);
            float e2 = __expf(s[n][2] - mn1);
            float e3 = __expf(s[n][3] - mn1);
            sum0 += e0 + e1; sum1 += e2 + e3;
            aP[n >> 1][(n & 1) * 2 + 0] = pack2(__float2half_rn(e0), __float2half_rn(e1));
            aP[n >> 1][(n & 1) * 2 + 1] = pack2(__float2half_rn(e2), __float2half_rn(e3));
        }
        sum0 += __shfl_xor_sync(0xffffffffu, sum0, 1);
        sum0 += __shfl_xor_sync(0xffffffffu, sum0, 2);
        sum1 += __shfl_xor_sync(0xffffffffu, sum1, 1);
        sum1 += __shfl_xor_sync(0xffffffffu, sum1, 2);
        l0 = l0 * cf0 + sum0;
        l1 = l1 * cf1 + sum1;

#pragma unroll
        for (int dn = 0; dn < 8; dn++) {
            o[dn][0] *= cf0; o[dn][1] *= cf0;
            o[dn][2] *= cf1; o[dn][3] *= cf1;
        }

        // O += P @ V ; V frags via ldmatrix.x4.trans (row-major V tile)
#pragma unroll
        for (int dn = 0; dn < 8; dn++) {
#pragma unroll
            for (int kp = 0; kp < 2; kp++) {
                uint32_t c00, c01, c10, c11;
                ldsm_x4_t(c00, c01, c10, c11,
                          vAddr + (kp * 32 * KSTR + dn * 8) * 2);
                mma16816(o[dn], aP[kp * 2], c00, c01);
                mma16816(o[dn], aP[kp * 2 + 1], c10, c11);
            }
        }
    }

    float inv0 = 1.f / l0, inv1 = 1.f / l1;
    int row0 = s0 + w * 16 + g, row1 = row0 + 8;
#pragma unroll
    for (int dn = 0; dn < 8; dn++) {
        int col = h * DD + dn * 8 + qr * 2;
        float2 v0 = make_float2(o[dn][0] * inv0, o[dn][1] * inv0);
        float2 v1 = make_float2(o[dn][2] * inv1, o[dn][3] * inv1);
        *(float2*)&out[(size_t)(b * SS + row0) * DE + col] = v0;
        *(float2*)&out[(size_t)(b * SS + row1) * DE + col] = v1;
    }
}

extern "C" void kernel_launch(void* const* d_in, const int* in_sizes, int n_in,
                              void* d_out, int out_size) {
    const float* k  = (const float*)d_in[0];
    const float* q  = (const float*)d_in[1];
    const float* v  = (const float*)d_in[2];
    const float* Wk = (const float*)d_in[3];
    const float* Wq = (const float*)d_in[4];
    const float* Wv = (const float*)d_in[5];
    float* out = (float*)d_out;

    dim3 pgrid(SS / 64, HH, 3 * BB);
    proj_kernel<<<pgrid, 128>>>(q, k, v, Wq, Wk, Wv);

    dim3 agrid(SS / 64, HH, BB);
    attn_kernel<<<agrid, 128>>>(out);
}